// round 1
// baseline (speedup 1.0000x reference)
#include <cuda_runtime.h>

// Problem constants (fixed by the reference)
#define BB 2
#define LL 2048
#define HH 12
#define DD 64
#define QT 16            // query rows per CTA
#define KT 64            // K/V rows per SMEM tile
#define SK_STRIDE 68     // padded row stride (floats) for K/V/Q tiles
#define SS_STRIDE (LL + 4)
#define NEWTON_ITERS 6
#define NTHREADS 256

// shared layout (floats):
//   sQ : QT * SK_STRIDE
//   sK : KT * SK_STRIDE   (reused for V in phase 3)
//   sS : QT * SS_STRIDE   (score row tile, then weights in-place)
#define SMEM_FLOATS ((QT + KT) * SK_STRIDE + QT * SS_STRIDE)
#define SMEM_BYTES (SMEM_FLOATS * 4)

__device__ __forceinline__ float frcp(float x) {
    float r;
    asm("rcp.approx.f32 %0, %1;" : "=f"(r) : "f"(x));
    return r;
}

extern __shared__ float smem[];

__global__ void __launch_bounds__(NTHREADS, 1)
poly_attn_kernel(const float* __restrict__ gq,
                 const float* __restrict__ gk,
                 const float* __restrict__ gv,
                 float* __restrict__ gout) {
    float* sQ = smem;
    float* sK = sQ + QT * SK_STRIDE;
    float* sS = sK + KT * SK_STRIDE;

    const int t  = threadIdx.x;
    const int q0 = blockIdx.x * QT;   // first query row of this tile
    const int h  = blockIdx.y;
    const int b  = blockIdx.z;

    // base offset of (b, row=0, h, d=0); row stride is H*D floats
    const size_t bh_base = (size_t)b * LL * (HH * DD) + (size_t)h * DD;
    const int row_stride = HH * DD;   // 768

    // ---- load Q tile (scaled by 1/sqrt(D) = 0.125) ----
    {
        int row = t >> 4;             // 0..15
        int c4  = (t & 15) * 4;       // 0..60
        float4 qv = *reinterpret_cast<const float4*>(
            gq + bh_base + (size_t)(q0 + row) * row_stride + c4);
        qv.x *= 0.125f; qv.y *= 0.125f; qv.z *= 0.125f; qv.w *= 0.125f;
        *reinterpret_cast<float4*>(sQ + row * SK_STRIDE + c4) = qv;
    }
    __syncthreads();

    // ---- Phase 1: scores S[qi][k] = q_qi . k_k ----
    const int tq = t >> 6;   // 0..3  (constant within each warp -> broadcast Q reads)
    const int tk = t & 63;   // 0..63
    for (int kt = 0; kt < LL / KT; ++kt) {
        // load K tile (64 rows x 64 floats)
        for (int idx = t; idx < KT * 16; idx += NTHREADS) {
            int row = idx >> 4;
            int c4  = (idx & 15) * 4;
            *reinterpret_cast<float4*>(sK + row * SK_STRIDE + c4) =
                *reinterpret_cast<const float4*>(
                    gk + bh_base + (size_t)(kt * KT + row) * row_stride + c4);
        }
        __syncthreads();

        float acc0 = 0.f, acc1 = 0.f, acc2 = 0.f, acc3 = 0.f;
        #pragma unroll
        for (int d4 = 0; d4 < DD; d4 += 4) {
            float4 kv  = *reinterpret_cast<const float4*>(sK + tk * SK_STRIDE + d4);
            float4 q0v = *reinterpret_cast<const float4*>(sQ + (tq     ) * SK_STRIDE + d4);
            float4 q1v = *reinterpret_cast<const float4*>(sQ + (tq +  4) * SK_STRIDE + d4);
            float4 q2v = *reinterpret_cast<const float4*>(sQ + (tq +  8) * SK_STRIDE + d4);
            float4 q3v = *reinterpret_cast<const float4*>(sQ + (tq + 12) * SK_STRIDE + d4);
            acc0 += q0v.x * kv.x + q0v.y * kv.y + q0v.z * kv.z + q0v.w * kv.w;
            acc1 += q1v.x * kv.x + q1v.y * kv.y + q1v.z * kv.z + q1v.w * kv.w;
            acc2 += q2v.x * kv.x + q2v.y * kv.y + q2v.z * kv.z + q2v.w * kv.w;
            acc3 += q3v.x * kv.x + q3v.y * kv.y + q3v.z * kv.z + q3v.w * kv.w;
        }
        int kcol = kt * KT + tk;
        sS[(tq     ) * SS_STRIDE + kcol] = acc0;
        sS[(tq +  4) * SS_STRIDE + kcol] = acc1;
        sS[(tq +  8) * SS_STRIDE + kcol] = acc2;
        sS[(tq + 12) * SS_STRIDE + kcol] = acc3;
        __syncthreads();
    }

    // ---- Phase 2: poly_norm per row (warp per row, 2 rows per warp) ----
    {
        const int wid  = t >> 5;
        const int lane = t & 31;
        for (int rr = 0; rr < 2; ++rr) {
            int row = wid + 8 * rr;
            float* srow = sS + row * SS_STRIDE;

            // c0 = -max(x) - 1
            float m = -3.402823466e38f;
            for (int i = lane; i < LL; i += 32) m = fmaxf(m, srow[i]);
            #pragma unroll
            for (int o = 16; o; o >>= 1) m = fmaxf(m, __shfl_xor_sync(0xffffffffu, m, o));
            float c = -m - 1.0f;

            // Newton: c -= (sum r^-2 - 1) / (2*sum r^-3 + eps),  r = -x - c
            for (int it = 0; it < NEWTON_ITERS; ++it) {
                float S = 0.f, Sd = 0.f;
                for (int i = lane; i < LL; i += 32) {
                    float r   = -srow[i] - c;
                    float inv = frcp(r);
                    float i2  = inv * inv;
                    S  += i2;
                    Sd += i2 * inv;
                }
                #pragma unroll
                for (int o = 16; o; o >>= 1) {
                    S  += __shfl_xor_sync(0xffffffffu, S,  o);
                    Sd += __shfl_xor_sync(0xffffffffu, Sd, o);
                }
                c = c - (S - 1.0f) / (2.0f * Sd + 1e-8f);
            }

            // weights in place: w = r^-2
            for (int i = lane; i < LL; i += 32) {
                float r   = -srow[i] - c;
                float inv = frcp(r);
                srow[i]   = inv * inv;
            }
        }
    }
    __syncthreads();

    // ---- Phase 3: out[qi][d] = sum_k w[qi][k] * V[k][d] ----
    {
        const int qi = t >> 4;          // 0..15
        const int d4 = (t & 15) * 4;    // 0..60
        float4 acc = make_float4(0.f, 0.f, 0.f, 0.f);
        for (int kt = 0; kt < LL / KT; ++kt) {
            // load V tile into sK
            for (int idx = t; idx < KT * 16; idx += NTHREADS) {
                int row = idx >> 4;
                int c4  = (idx & 15) * 4;
                *reinterpret_cast<float4*>(sK + row * SK_STRIDE + c4) =
                    *reinterpret_cast<const float4*>(
                        gv + bh_base + (size_t)(kt * KT + row) * row_stride + c4);
            }
            __syncthreads();

            const float* wrow = sS + qi * SS_STRIDE + kt * KT;
            #pragma unroll 8
            for (int kk = 0; kk < KT; ++kk) {
                float  w  = wrow[kk];
                float4 vv = *reinterpret_cast<const float4*>(sK + kk * SK_STRIDE + d4);
                acc.x += w * vv.x;
                acc.y += w * vv.y;
                acc.z += w * vv.z;
                acc.w += w * vv.w;
            }
            __syncthreads();   // before next tile overwrites sK
        }
        *reinterpret_cast<float4*>(
            gout + bh_base + (size_t)(q0 + qi) * row_stride + d4) = acc;
    }
}

extern "C" void kernel_launch(void* const* d_in, const int* in_sizes, int n_in,
                              void* d_out, int out_size) {
    const float* q = (const float*)d_in[0];
    const float* k = (const float*)d_in[1];
    const float* v = (const float*)d_in[2];
    float* out = (float*)d_out;

    cudaFuncSetAttribute(poly_attn_kernel,
                         cudaFuncAttributeMaxDynamicSharedMemorySize, SMEM_BYTES);

    dim3 grid(LL / QT, HH, BB);
    poly_attn_kernel<<<grid, NTHREADS, SMEM_BYTES>>>(q, k, v, out);
}

// round 2
// speedup vs baseline: 2.2372x; 2.2372x over previous
#include <cuda_runtime.h>

// Problem constants (fixed by the reference)
#define BB 2
#define LL 2048
#define HH 12
#define DD 64
#define QT 16            // query rows per CTA
#define KT 256           // K/V rows per SMEM tile
#define NKT (LL / KT)    // 8 tiles
#define SK_STRIDE 68     // padded row stride (floats) for K/V/Q tiles
#define SS_STRIDE (LL + 4)
#define NEWTON_ITERS 6
#define NTHREADS 512
#define ROW_STRIDE (HH * DD)   // 768 floats between consecutive seq rows

// shared layout (floats):
//   sQ : QT * SK_STRIDE
//   sK : KT * SK_STRIDE   (reused for V in phase 3)
//   sS : QT * SS_STRIDE   (score tile -> weights in place -> partial buffer)
#define SMEM_FLOATS ((QT + KT) * SK_STRIDE + QT * SS_STRIDE)
#define SMEM_BYTES (SMEM_FLOATS * 4)

__device__ __forceinline__ float frcp(float x) {
    float r;
    asm("rcp.approx.f32 %0, %1;" : "=f"(r) : "f"(x));
    return r;
}

extern __shared__ float smem[];

__global__ void __launch_bounds__(NTHREADS, 1)
poly_attn_kernel(const float* __restrict__ gq,
                 const float* __restrict__ gk,
                 const float* __restrict__ gv,
                 float* __restrict__ gout) {
    float* sQ = smem;
    float* sK = sQ + QT * SK_STRIDE;
    float* sS = sK + KT * SK_STRIDE;

    const int t    = threadIdx.x;
    const int lane = t & 31;
    const int warp = t >> 5;
    const int q0   = blockIdx.x * QT;
    const int h    = blockIdx.y;
    const int b    = blockIdx.z;

    const size_t bh_base = (size_t)b * LL * ROW_STRIDE + (size_t)h * DD;

    // ---- load Q tile (scaled by 1/sqrt(D) = 0.125) ----
    if (t < QT * 16) {
        int row = t >> 4;
        int c4  = (t & 15) * 4;
        float4 qv = *reinterpret_cast<const float4*>(
            gq + bh_base + (size_t)(q0 + row) * ROW_STRIDE + c4);
        qv.x *= 0.125f; qv.y *= 0.125f; qv.z *= 0.125f; qv.w *= 0.125f;
        *reinterpret_cast<float4*>(sQ + row * SK_STRIDE + c4) = qv;
    }
    __syncthreads();

    // ==== Phase 1: scores S[qi][k] = q_qi . k_k ====
    // warp layout: qg = warp & 3 (q-quad, broadcast Q reads), kb = warp >> 2
    // each thread: 4 q rows x 2 k cols (lane, lane+32 within its 64-k block)
    {
        const int qg = warp & 3;
        const int kb = warp >> 2;
        const int k0 = kb * 64 + lane;      // within tile

        for (int kt = 0; kt < NKT; ++kt) {
            // cooperative load of K tile (256 rows x 64 floats)
            for (int i = t; i < KT * 16; i += NTHREADS) {
                int row = i >> 4;
                int c4  = (i & 15) * 4;
                *reinterpret_cast<float4*>(sK + row * SK_STRIDE + c4) =
                    *reinterpret_cast<const float4*>(
                        gk + bh_base + (size_t)(kt * KT + row) * ROW_STRIDE + c4);
            }
            __syncthreads();

            float a00=0.f,a01=0.f,a10=0.f,a11=0.f,a20=0.f,a21=0.f,a30=0.f,a31=0.f;
            const float* kp0 = sK + k0 * SK_STRIDE;
            const float* kp1 = sK + (k0 + 32) * SK_STRIDE;
            #pragma unroll
            for (int d4 = 0; d4 < DD; d4 += 4) {
                float4 kv0 = *reinterpret_cast<const float4*>(kp0 + d4);
                float4 kv1 = *reinterpret_cast<const float4*>(kp1 + d4);
                float4 qa = *reinterpret_cast<const float4*>(sQ + (qg     ) * SK_STRIDE + d4);
                float4 qb = *reinterpret_cast<const float4*>(sQ + (qg +  4) * SK_STRIDE + d4);
                float4 qc = *reinterpret_cast<const float4*>(sQ + (qg +  8) * SK_STRIDE + d4);
                float4 qd = *reinterpret_cast<const float4*>(sQ + (qg + 12) * SK_STRIDE + d4);
                a00 += qa.x*kv0.x + qa.y*kv0.y + qa.z*kv0.z + qa.w*kv0.w;
                a01 += qa.x*kv1.x + qa.y*kv1.y + qa.z*kv1.z + qa.w*kv1.w;
                a10 += qb.x*kv0.x + qb.y*kv0.y + qb.z*kv0.z + qb.w*kv0.w;
                a11 += qb.x*kv1.x + qb.y*kv1.y + qb.z*kv1.z + qb.w*kv1.w;
                a20 += qc.x*kv0.x + qc.y*kv0.y + qc.z*kv0.z + qc.w*kv0.w;
                a21 += qc.x*kv1.x + qc.y*kv1.y + qc.z*kv1.z + qc.w*kv1.w;
                a30 += qd.x*kv0.x + qd.y*kv0.y + qd.z*kv0.z + qd.w*kv0.w;
                a31 += qd.x*kv1.x + qd.y*kv1.y + qd.z*kv1.z + qd.w*kv1.w;
            }
            int kcol = kt * KT + k0;
            sS[(qg     ) * SS_STRIDE + kcol] = a00;
            sS[(qg     ) * SS_STRIDE + kcol + 32] = a01;
            sS[(qg +  4) * SS_STRIDE + kcol] = a10;
            sS[(qg +  4) * SS_STRIDE + kcol + 32] = a11;
            sS[(qg +  8) * SS_STRIDE + kcol] = a20;
            sS[(qg +  8) * SS_STRIDE + kcol + 32] = a21;
            sS[(qg + 12) * SS_STRIDE + kcol] = a30;
            sS[(qg + 12) * SS_STRIDE + kcol + 32] = a31;
            __syncthreads();
        }
    }

    // ==== Phase 2: poly_norm, one warp per score row ====
    {
        float* srow = sS + warp * SS_STRIDE;
        const float* lp = srow + lane * 4;

        // c0 = -max(x) - 1
        float m = -3.402823466e38f;
        #pragma unroll
        for (int j = 0; j < LL / 128; ++j) {
            float4 v = *reinterpret_cast<const float4*>(lp + j * 128);
            m = fmaxf(m, fmaxf(fmaxf(v.x, v.y), fmaxf(v.z, v.w)));
        }
        #pragma unroll
        for (int o = 16; o; o >>= 1) m = fmaxf(m, __shfl_xor_sync(0xffffffffu, m, o));
        float c = -m - 1.0f;

        for (int it = 0; it < NEWTON_ITERS; ++it) {
            float S = 0.f, Sd = 0.f;
            #pragma unroll
            for (int j = 0; j < LL / 128; ++j) {
                float4 v = *reinterpret_cast<const float4*>(lp + j * 128);
                float i0 = frcp(-v.x - c), i1 = frcp(-v.y - c);
                float i2 = frcp(-v.z - c), i3 = frcp(-v.w - c);
                float s0 = i0*i0, s1 = i1*i1, s2 = i2*i2, s3 = i3*i3;
                S  += (s0 + s1) + (s2 + s3);
                Sd += (s0*i0 + s1*i1) + (s2*i2 + s3*i3);
            }
            #pragma unroll
            for (int o = 16; o; o >>= 1) {
                S  += __shfl_xor_sync(0xffffffffu, S,  o);
                Sd += __shfl_xor_sync(0xffffffffu, Sd, o);
            }
            c = c - (S - 1.0f) / (2.0f * Sd + 1e-8f);
        }

        // weights in place: w = (-x - c)^-2
        #pragma unroll
        for (int j = 0; j < LL / 128; ++j) {
            float4 v = *reinterpret_cast<float4*>(srow + lane * 4 + j * 128);
            float i0 = frcp(-v.x - c), i1 = frcp(-v.y - c);
            float i2 = frcp(-v.z - c), i3 = frcp(-v.w - c);
            v.x = i0*i0; v.y = i1*i1; v.z = i2*i2; v.w = i3*i3;
            *reinterpret_cast<float4*>(srow + lane * 4 + j * 128) = v;
        }
    }
    __syncthreads();

    // ==== Phase 3: out[qi][d] = sum_k w[qi][k] * V[k][d], split-k x8 ====
    // thread: kg = t>>6 (k group), qs = (t>>4)&3, d4i = t&15
    // computes 4 q rows {qs, qs+4, qs+8, qs+12} x float4 at col d4i*4
    {
        const int kg  = t >> 6;
        const int qs  = (t >> 4) & 3;
        const int d4  = (t & 15) * 4;
        float4 acc0 = {0,0,0,0}, acc1 = {0,0,0,0}, acc2 = {0,0,0,0}, acc3 = {0,0,0,0};

        for (int kt = 0; kt < NKT; ++kt) {
            // cooperative load of V tile
            for (int i = t; i < KT * 16; i += NTHREADS) {
                int row = i >> 4;
                int c4  = (i & 15) * 4;
                *reinterpret_cast<float4*>(sK + row * SK_STRIDE + c4) =
                    *reinterpret_cast<const float4*>(
                        gv + bh_base + (size_t)(kt * KT + row) * ROW_STRIDE + c4);
            }
            __syncthreads();

            const int kbase = kg * 32;
            const float* w0 = sS + (qs     ) * SS_STRIDE + kt * KT + kbase;
            const float* w1 = sS + (qs +  4) * SS_STRIDE + kt * KT + kbase;
            const float* w2 = sS + (qs +  8) * SS_STRIDE + kt * KT + kbase;
            const float* w3 = sS + (qs + 12) * SS_STRIDE + kt * KT + kbase;
            const float* vp = sK + kbase * SK_STRIDE + d4;
            #pragma unroll 8
            for (int kk = 0; kk < 32; ++kk) {
                float4 vv = *reinterpret_cast<const float4*>(vp + kk * SK_STRIDE);
                float f0 = w0[kk], f1 = w1[kk], f2 = w2[kk], f3 = w3[kk];
                acc0.x += f0*vv.x; acc0.y += f0*vv.y; acc0.z += f0*vv.z; acc0.w += f0*vv.w;
                acc1.x += f1*vv.x; acc1.y += f1*vv.y; acc1.z += f1*vv.z; acc1.w += f1*vv.w;
                acc2.x += f2*vv.x; acc2.y += f2*vv.y; acc2.z += f2*vv.z; acc2.w += f2*vv.w;
                acc3.x += f3*vv.x; acc3.y += f3*vv.y; acc3.z += f3*vv.z; acc3.w += f3*vv.w;
            }
            __syncthreads();
        }

        // all weight reads done -> safe to overwrite sS with partials
        __syncthreads();
        // partial layout: [kg][q][d4i] float4
        float4* sP = reinterpret_cast<float4*>(sS);
        sP[(kg * QT + qs     ) * 16 + (t & 15)] = acc0;
        sP[(kg * QT + qs +  4) * 16 + (t & 15)] = acc1;
        sP[(kg * QT + qs +  8) * 16 + (t & 15)] = acc2;
        sP[(kg * QT + qs + 12) * 16 + (t & 15)] = acc3;
        __syncthreads();

        if (t < QT * 16) {
            int q   = t >> 4;
            int dc  = t & 15;
            float4 s = sP[(0 * QT + q) * 16 + dc];
            #pragma unroll
            for (int g = 1; g < 8; ++g) {
                float4 p = sP[(g * QT + q) * 16 + dc];
                s.x += p.x; s.y += p.y; s.z += p.z; s.w += p.w;
            }
            *reinterpret_cast<float4*>(
                gout + bh_base + (size_t)(q0 + q) * ROW_STRIDE + dc * 4) = s;
        }
    }
}

extern "C" void kernel_launch(void* const* d_in, const int* in_sizes, int n_in,
                              void* d_out, int out_size) {
    const float* q = (const float*)d_in[0];
    const float* k = (const float*)d_in[1];
    const float* v = (const float*)d_in[2];
    float* out = (float*)d_out;

    cudaFuncSetAttribute(poly_attn_kernel,
                         cudaFuncAttributeMaxDynamicSharedMemorySize, SMEM_BYTES);

    dim3 grid(LL / QT, HH, BB);
    poly_attn_kernel<<<grid, NTHREADS, SMEM_BYTES>>>(q, k, v, out);
}

// round 3
// speedup vs baseline: 2.7293x; 1.2200x over previous
#include <cuda_runtime.h>

// Problem constants (fixed by the reference)
#define BB 2
#define LL 2048
#define HH 12
#define DD 64
#define QT 16            // query rows per CTA
#define KT 256           // K/V rows per SMEM tile
#define NKT (LL / KT)    // 8 tiles
#define SK_STRIDE 68     // padded row stride (floats) for K/V/Q tiles
#define SS_STRIDE (LL + 4)   // 2052
#define SP_STRIDE 1028   // padded stride for split-k partials (QT*DD + 4)
#define NEWTON_ITERS 6
#define NTHREADS 512
#define ROW_STRIDE (HH * DD)   // 768 floats between consecutive seq rows

#define SMEM_FLOATS ((QT + KT) * SK_STRIDE + QT * SS_STRIDE)
#define SMEM_BYTES (SMEM_FLOATS * 4)

__device__ __forceinline__ float frcp(float x) {
    float r;
    asm("rcp.approx.f32 %0, %1;" : "=f"(r) : "f"(x));
    return r;
}

__device__ __forceinline__ unsigned f2tf32(float x) {
    unsigned u;
    asm("cvt.rna.tf32.f32 %0, %1;" : "=r"(u) : "f"(x));
    return u;
}

// d += A(16x8,row) * B(8x8,col) in tf32
__device__ __forceinline__ void mma8(float4& d,
                                     unsigned a0, unsigned a1, unsigned a2, unsigned a3,
                                     unsigned b0, unsigned b1) {
    asm volatile(
        "mma.sync.aligned.m16n8k8.row.col.f32.tf32.tf32.f32 "
        "{%0,%1,%2,%3}, {%4,%5,%6,%7}, {%8,%9}, {%0,%1,%2,%3};\n"
        : "+f"(d.x), "+f"(d.y), "+f"(d.z), "+f"(d.w)
        : "r"(a0), "r"(a1), "r"(a2), "r"(a3), "r"(b0), "r"(b1));
}

extern __shared__ float smem[];

__global__ void __launch_bounds__(NTHREADS, 1)
poly_attn_kernel(const float* __restrict__ gq,
                 const float* __restrict__ gk,
                 const float* __restrict__ gv,
                 float* __restrict__ gout) {
    float* sQ = smem;
    float* sK = sQ + QT * SK_STRIDE;          // K tile, reused for V
    float* sS = sK + KT * SK_STRIDE;          // scores -> weights -> partials

    const int t    = threadIdx.x;
    const int lane = t & 31;
    const int warp = t >> 5;
    const int g    = lane >> 2;   // mma group id (0..7)
    const int r    = lane & 3;    // thread in group (0..3)
    const int q0   = blockIdx.x * QT;
    const int h    = blockIdx.y;
    const int b    = blockIdx.z;

    const size_t bh_base = (size_t)b * LL * ROW_STRIDE + (size_t)h * DD;

    // ---- load Q tile (scaled by 1/sqrt(D) = 0.125) ----
    if (t < QT * 16) {
        int row = t >> 4;
        int c4  = (t & 15) * 4;
        float4 qv = *reinterpret_cast<const float4*>(
            gq + bh_base + (size_t)(q0 + row) * ROW_STRIDE + c4);
        qv.x *= 0.125f; qv.y *= 0.125f; qv.z *= 0.125f; qv.w *= 0.125f;
        *reinterpret_cast<float4*>(sQ + row * SK_STRIDE + c4) = qv;
    }
    __syncthreads();

    // ==== Phase 1: S = Q K^T via 3xTF32 mma ====
    {
        // A fragments for all 8 k-steps (d-dim), hi/lo split, held in regs.
        unsigned ah[8][4], al[8][4];
        #pragma unroll
        for (int ks = 0; ks < 8; ++ks) {
            int d0 = ks * 8;
            float f0 = sQ[(g    ) * SK_STRIDE + d0 + r];
            float f1 = sQ[(g + 8) * SK_STRIDE + d0 + r];
            float f2 = sQ[(g    ) * SK_STRIDE + d0 + r + 4];
            float f3 = sQ[(g + 8) * SK_STRIDE + d0 + r + 4];
            ah[ks][0] = f2tf32(f0); al[ks][0] = __float_as_uint(f0 - __uint_as_float(ah[ks][0]));
            ah[ks][1] = f2tf32(f1); al[ks][1] = __float_as_uint(f1 - __uint_as_float(ah[ks][1]));
            ah[ks][2] = f2tf32(f2); al[ks][2] = __float_as_uint(f2 - __uint_as_float(ah[ks][2]));
            ah[ks][3] = f2tf32(f3); al[ks][3] = __float_as_uint(f3 - __uint_as_float(ah[ks][3]));
        }

        for (int kt = 0; kt < NKT; ++kt) {
            // cooperative load of K tile (256 rows x 64 floats)
            for (int i = t; i < KT * 16; i += NTHREADS) {
                int row = i >> 4;
                int c4  = (i & 15) * 4;
                *reinterpret_cast<float4*>(sK + row * SK_STRIDE + c4) =
                    *reinterpret_cast<const float4*>(
                        gk + bh_base + (size_t)(kt * KT + row) * ROW_STRIDE + c4);
            }
            __syncthreads();

            #pragma unroll
            for (int nt = 0; nt < 2; ++nt) {
                int n0 = (warp * 2 + nt) * 8;   // token block within tile
                float4 c = make_float4(0.f, 0.f, 0.f, 0.f);
                #pragma unroll
                for (int ks = 0; ks < 8; ++ks) {
                    const float* kp = sK + (n0 + g) * SK_STRIDE + ks * 8 + r;
                    float bb0 = kp[0];
                    float bb1 = kp[4];
                    unsigned b0h = f2tf32(bb0), b1h = f2tf32(bb1);
                    unsigned b0l = __float_as_uint(bb0 - __uint_as_float(b0h));
                    unsigned b1l = __float_as_uint(bb1 - __uint_as_float(b1h));
                    mma8(c, ah[ks][0], ah[ks][1], ah[ks][2], ah[ks][3], b0h, b1h);
                    mma8(c, ah[ks][0], ah[ks][1], ah[ks][2], ah[ks][3], b0l, b1l);
                    mma8(c, al[ks][0], al[ks][1], al[ks][2], al[ks][3], b0h, b1h);
                }
                int col = kt * KT + n0 + 2 * r;
                *reinterpret_cast<float2*>(sS + (g    ) * SS_STRIDE + col) = make_float2(c.x, c.y);
                *reinterpret_cast<float2*>(sS + (g + 8) * SS_STRIDE + col) = make_float2(c.z, c.w);
            }
            __syncthreads();
        }
    }

    // ==== Phase 2: poly_norm, one warp per score row ====
    {
        float* srow = sS + warp * SS_STRIDE;
        const float* lp = srow + lane * 4;

        float m = -3.402823466e38f;
        #pragma unroll
        for (int j = 0; j < LL / 128; ++j) {
            float4 v = *reinterpret_cast<const float4*>(lp + j * 128);
            m = fmaxf(m, fmaxf(fmaxf(v.x, v.y), fmaxf(v.z, v.w)));
        }
        #pragma unroll
        for (int o = 16; o; o >>= 1) m = fmaxf(m, __shfl_xor_sync(0xffffffffu, m, o));
        float c = -m - 1.0f;

        for (int it = 0; it < NEWTON_ITERS; ++it) {
            float S = 0.f, Sd = 0.f;
            #pragma unroll
            for (int j = 0; j < LL / 128; ++j) {
                float4 v = *reinterpret_cast<const float4*>(lp + j * 128);
                float i0 = frcp(-v.x - c), i1 = frcp(-v.y - c);
                float i2 = frcp(-v.z - c), i3 = frcp(-v.w - c);
                float s0 = i0*i0, s1 = i1*i1, s2 = i2*i2, s3 = i3*i3;
                S  += (s0 + s1) + (s2 + s3);
                Sd += (s0*i0 + s1*i1) + (s2*i2 + s3*i3);
            }
            #pragma unroll
            for (int o = 16; o; o >>= 1) {
                S  += __shfl_xor_sync(0xffffffffu, S,  o);
                Sd += __shfl_xor_sync(0xffffffffu, Sd, o);
            }
            c = c - (S - 1.0f) / (2.0f * Sd + 1e-8f);
        }

        #pragma unroll
        for (int j = 0; j < LL / 128; ++j) {
            float4 v = *reinterpret_cast<float4*>(srow + lane * 4 + j * 128);
            float i0 = frcp(-v.x - c), i1 = frcp(-v.y - c);
            float i2 = frcp(-v.z - c), i3 = frcp(-v.w - c);
            v.x = i0*i0; v.y = i1*i1; v.z = i2*i2; v.w = i3*i3;
            *reinterpret_cast<float4*>(srow + lane * 4 + j * 128) = v;
        }
    }
    __syncthreads();

    // ==== Phase 3: O = W V via 3xTF32 mma, split-k across warps ====
    {
        float4 C[8];
        #pragma unroll
        for (int nt = 0; nt < 8; ++nt) C[nt] = make_float4(0.f, 0.f, 0.f, 0.f);

        for (int kt = 0; kt < NKT; ++kt) {
            // cooperative load of V tile into sK
            for (int i = t; i < KT * 16; i += NTHREADS) {
                int row = i >> 4;
                int c4  = (i & 15) * 4;
                *reinterpret_cast<float4*>(sK + row * SK_STRIDE + c4) =
                    *reinterpret_cast<const float4*>(
                        gv + bh_base + (size_t)(kt * KT + row) * ROW_STRIDE + c4);
            }
            __syncthreads();

            #pragma unroll
            for (int ks2 = 0; ks2 < 2; ++ks2) {
                int kloc = warp * 16 + ks2 * 8;         // k rows within tile
                int kgl  = kt * KT + kloc;              // global k
                // A = W fragments (rows g, g+8; cols kgl+r, kgl+r+4)
                float w0 = sS[(g    ) * SS_STRIDE + kgl + r];
                float w1 = sS[(g + 8) * SS_STRIDE + kgl + r];
                float w2 = sS[(g    ) * SS_STRIDE + kgl + r + 4];
                float w3 = sS[(g + 8) * SS_STRIDE + kgl + r + 4];
                unsigned ah0 = f2tf32(w0), ah1 = f2tf32(w1);
                unsigned ah2 = f2tf32(w2), ah3 = f2tf32(w3);
                unsigned al0 = __float_as_uint(w0 - __uint_as_float(ah0));
                unsigned al1 = __float_as_uint(w1 - __uint_as_float(ah1));
                unsigned al2 = __float_as_uint(w2 - __uint_as_float(ah2));
                unsigned al3 = __float_as_uint(w3 - __uint_as_float(ah3));

                #pragma unroll
                for (int nt = 0; nt < 8; ++nt) {
                    float vb0 = sK[(kloc + r    ) * SK_STRIDE + nt * 8 + g];
                    float vb1 = sK[(kloc + r + 4) * SK_STRIDE + nt * 8 + g];
                    unsigned b0h = f2tf32(vb0), b1h = f2tf32(vb1);
                    unsigned b0l = __float_as_uint(vb0 - __uint_as_float(b0h));
                    unsigned b1l = __float_as_uint(vb1 - __uint_as_float(b1h));
                    mma8(C[nt], ah0, ah1, ah2, ah3, b0h, b1h);
                    mma8(C[nt], ah0, ah1, ah2, ah3, b0l, b1l);
                    mma8(C[nt], al0, al1, al2, al3, b0h, b1h);
                }
            }
            __syncthreads();
        }

        // write split-k partials into sS (weights fully consumed)
        float* sP = sS;
        #pragma unroll
        for (int nt = 0; nt < 8; ++nt) {
            int d0 = nt * 8 + 2 * r;
            *reinterpret_cast<float2*>(sP + warp * SP_STRIDE + (g    ) * DD + d0) =
                make_float2(C[nt].x, C[nt].y);
            *reinterpret_cast<float2*>(sP + warp * SP_STRIDE + (g + 8) * DD + d0) =
                make_float2(C[nt].z, C[nt].w);
        }
        __syncthreads();

        // reduce 16 partials and store
        for (int o = t; o < QT * DD; o += NTHREADS) {
            float s = 0.f;
            #pragma unroll
            for (int w = 0; w < 16; ++w) s += sP[w * SP_STRIDE + o];
            int q  = o >> 6;
            int dc = o & 63;
            gout[bh_base + (size_t)(q0 + q) * ROW_STRIDE + dc] = s;
        }
    }
}

extern "C" void kernel_launch(void* const* d_in, const int* in_sizes, int n_in,
                              void* d_out, int out_size) {
    const float* q = (const float*)d_in[0];
    const float* k = (const float*)d_in[1];
    const float* v = (const float*)d_in[2];
    float* out = (float*)d_out;

    cudaFuncSetAttribute(poly_attn_kernel,
                         cudaFuncAttributeMaxDynamicSharedMemorySize, SMEM_BYTES);

    dim3 grid(LL / QT, HH, BB);
    poly_attn_kernel<<<grid, NTHREADS, SMEM_BYTES>>>(q, k, v, out);
}